// round 12
// baseline (speedup 1.0000x reference)
#include <cuda_runtime.h>
#include <stdint.h>

// ---------------- problem constants (fixed shapes from reference) ----------------
#define RAWN   40962u                   // ico-6 nodes
#define FEATN  256
#define NELEM  (RAWN * 256u)            // 10486272 flat elements
#define NDIV   (NELEM - 1u)             // 10486271 linspace divisor
#define NNODES 163842
#define OUTSZ  ((size_t)NNODES * FEATN) // 41943552 output floats
#define N4     (OUTSZ / 4)              // float4 count for zeroing

#define NR        256                   // one scatter block per output column r
#define ZBLOCKS   2048
#define TOTAL_BLOCKS (NR + ZBLOCKS)     // 2304 = 9 * 256 -> perfect interleave
#define HSIZE     2048                  // smem hash slots (>= 1127 max distinct cells)
#define K2BLOCKS  ((NR * HSIZE) / 256)  // 2048

// Scratch: per-r hash-table dumps, FULLY rewritten every launch (incl. empty slots)
// -> no reset pass needed, replay-deterministic. e.x = c+1 (0 = empty), e.y = valbits.
__device__ uint2 g_out[NR * HSIZE];     // 4 MB

// ---------------------------------------------------------------------------------
// smem hash: open addressing; tag = c+1 claimed by CAS, value arbitration by
// 64-bit smem atomicMax on packed ((k+1)<<32 | float_bits) -> max flat-k wins.
// Probe loop is provably terminating (load <= 1127/2048) but bounded anyway.
// ---------------------------------------------------------------------------------
__device__ __forceinline__ void hash_insert(unsigned* tag, unsigned long long* pk,
                                            unsigned c, unsigned long long v)
{
    unsigned h = (c * 2654435761u) >> 21;           // top 11 bits -> [0,2048)
    #pragma unroll 1
    for (int it = 0; it < 2 * HSIZE; ++it) {
        const unsigned t = *(volatile unsigned*)&tag[h];
        if (t == c + 1u) break;                     // already claimed for this c
        if (t == 0u) {
            const unsigned old = atomicCAS(&tag[h], 0u, c + 1u);
            if (old == 0u || old == c + 1u) break;  // claimed (by us or same-c peer)
            // different c raced in: fall through to re-examine (now nonzero)
            if (old != c + 1u) { h = (h + 1u) & (HSIZE - 1u); }
        } else {
            h = (h + 1u) & (HSIZE - 1u);
        }
    }
    atomicMax(&pk[h], v);
}

// ---------------------------------------------------------------------------------
// Scatter block for output column r: processes the contiguous k-interval with
// floor(k*256/NDIV)==r (~161 source rows). All its cells are c*256+r -> disjoint
// from every other block, so arbitration is purely block-local (smem hash).
// ---------------------------------------------------------------------------------
template <typename IT>
__device__ __forceinline__ void scatter_r(
    int r, unsigned* tag, unsigned long long* pk,
    const float* __restrict__ x,
    const IT*    __restrict__ max_index,
    const IT*    __restrict__ neigh)
{
    const int tid  = threadIdx.x;
    const int w    = tid >> 5;
    const int lane = tid & 31;

    // k-interval for this r:  k in [ceil(r*NDIV/256), ceil((r+1)*NDIV/256)-1]
    const unsigned k_lo = ((unsigned)r * NDIV + 255u) / 256u;
    unsigned       k_hi = (((unsigned)r + 1u) * NDIV + 255u) / 256u - 1u;
    if (r == NR - 1) k_hi = NELEM - 1u;   // final element: linspace end clamped to 255

    // init hash
    #pragma unroll
    for (int s = tid; s < HSIZE; s += 256) { tag[s] = 0u; pk[s] = 0ull; }
    __syncthreads();

    const int i_lo = (int)(k_lo >> 8);
    const int i_hi = (int)(k_hi >> 8);

    for (int i = i_lo + w; i <= i_hi; i += 8) {     // warp-per-row, 8 warps striding
        const IT* mi = max_index + (size_t)i * FEATN;
        int mval[8];
        #pragma unroll
        for (int j = 0; j < 8; ++j) mval[j] = (int)__ldcs(&mi[j * 32 + lane]);

        unsigned taken = 0;                          // cell slots m = 0..6
        #pragma unroll
        for (int j = 7; j >= 0; --j) {               // descending f: first win = max f
            const int f = j * 32 + lane;
            const unsigned k = (unsigned)i * 256u + (unsigned)f;
            const bool valid = (k >= k_lo) & (k <= k_hi);
            const int slot = valid ? mval[j] : (8 + lane);   // invalid -> unique dummy

            const unsigned peers  = __match_any_sync(0xffffffffu, slot);
            const int      leader = 31 - __clz(peers);
            const bool     win    = valid && (lane == leader) && !((taken >> slot) & 1u);
            const unsigned rslots = __reduce_or_sync(0xffffffffu, valid ? (1u << slot) : 0u);

            if (win) {
                const unsigned c = (unsigned)neigh[(size_t)i * 7 + slot];
                const unsigned long long v =
                    ((unsigned long long)(k + 1u) << 32) |
                    (unsigned long long)__float_as_uint(x[(size_t)i * FEATN + f]);
                hash_insert(tag, pk, c, v);
            }
            taken |= rslots;
        }
    }
    __syncthreads();

    // flush: every slot written (occupied or zero) -> g_out fully refreshed, no reset
    uint2* out = g_out + (size_t)r * HSIZE;
    #pragma unroll
    for (int s = tid; s < HSIZE; s += 256) {
        const unsigned t = tag[s];
        out[s] = make_uint2(t, t ? (unsigned)(pk[s] & 0xffffffffull) : 0u);
    }
}

// ---------------------------------------------------------------------------------
// K1: interleaved roles, period 9 = 1 scatter + 8 zero, so every resident wave
// carries both the latency-bound scatter work and the BW-bound zero stream.
// ---------------------------------------------------------------------------------
__global__ void __launch_bounds__(256)
k1_main(const float* __restrict__ x,
        const void*  __restrict__ mi_raw,
        const void*  __restrict__ ng_raw,
        float* __restrict__ y)
{
    __shared__ unsigned           s_tag[HSIZE];
    __shared__ unsigned long long s_pk[HSIZE];

    const unsigned bid = blockIdx.x;
    if (bid % 9u != 0u) {
        // zeroing role: 168 MB of streaming float4 stores, no loads
        const unsigned zb = bid - bid / 9u - 1u;            // 0..2047
        float4* y4 = reinterpret_cast<float4*>(y);
        const size_t stride = (size_t)ZBLOCKS * 256;
        size_t idx = (size_t)zb * 256 + threadIdx.x;
        const float4 z = make_float4(0.f, 0.f, 0.f, 0.f);
        for (size_t p = idx; p < (size_t)N4; p += stride) __stcs(&y4[p], z);
        return;
    }

    const int r = (int)(bid / 9u);                          // 0..255

    // Index-dtype detection (JAX x64 disabled silently yields int32 despite jnp.int64).
    // int64 buffer: high words of first 8 neigh entries all 0; int32: random ids.
    const uint2* probe = reinterpret_cast<const uint2*>(ng_raw);
    unsigned hiw = 0;
    #pragma unroll
    for (int t = 0; t < 8; ++t) hiw |= probe[t].y;

    if (hiw == 0)
        scatter_r<long long>(r, s_tag, s_pk, x,
                             (const long long*)mi_raw, (const long long*)ng_raw);
    else
        scatter_r<int>(r, s_tag, s_pk, x,
                       (const int*)mi_raw, (const int*)ng_raw);
}

// ---------------------------------------------------------------------------------
// K2: store-only commit. Coalesced 8B entry read -> fire-and-forget scattered
// store. No scattered reads, no atomics, no resets.
// ---------------------------------------------------------------------------------
__global__ void __launch_bounds__(256)
k2_commit(float* __restrict__ y)
{
    const unsigned q = blockIdx.x * 256u + threadIdx.x;     // < NR*HSIZE
    const unsigned r = q >> 11;                             // q / HSIZE
    const uint2 e = g_out[q];
    if (e.x)
        y[(size_t)(e.x - 1u) * 256u + r] = __uint_as_float(e.y);
}

// ---------------------------------------------------------------------------------
extern "C" void kernel_launch(void* const* d_in, const int* in_sizes, int n_in,
                              void* d_out, int out_size)
{
    const float* x  = (const float*)d_in[0];
    const void*  mi = (const void*)d_in[1];   // int32 or int64, auto-detected on device
    const void*  ng = (const void*)d_in[2];
    float*       y  = (float*)d_out;

    (void)in_sizes; (void)n_in; (void)out_size;

    k1_main<<<TOTAL_BLOCKS, 256>>>(x, mi, ng, y);
    k2_commit<<<K2BLOCKS, 256>>>(y);
}